// round 2
// baseline (speedup 1.0000x reference)
#include <cuda_runtime.h>
#include <math.h>

#define D   256
#define NQ  512
#define NK  512

typedef unsigned long long ull;

// ---------------- scratch ----------------
__device__ __align__(16) float g_aq[D * NQ];      // (d, n)
__device__ __align__(16) float g_ak[D * NK];      // (d, m)
__device__ __align__(16) float g_probT[NK * NQ];  // (m, n)  transposed prob
__device__ __align__(16) float g_msg[D * NQ];     // (d, n)
__device__ __align__(16) float g_h2[2 * D * NQ];  // (o, n)

// ---------------- f32x2 helpers ----------------
__device__ __forceinline__ ull pack2(float lo, float hi) {
    ull r; asm("mov.b64 %0,{%1,%2};" : "=l"(r) : "f"(lo), "f"(hi)); return r;
}
__device__ __forceinline__ float2 unpack2(ull v) {
    float2 r; asm("mov.b64 {%0,%1},%2;" : "=f"(r.x), "=f"(r.y) : "l"(v)); return r;
}
__device__ __forceinline__ ull fma2(ull a, ull b, ull c) {
    ull d; asm("fma.rn.f32x2 %0,%1,%2,%3;" : "=l"(d) : "l"(a), "l"(b), "l"(c)); return d;
}
__device__ __forceinline__ ull add2(ull a, ull b) {
    ull d; asm("add.rn.f32x2 %0,%1,%2;" : "=l"(d) : "l"(a), "l"(b)); return d;
}

// ---------------- packed-f32x2 SGEMM core ----------------
// out[o0..o0+BM-1][n0..n0+63] = act(sum_k W[o][k]*X[k][n] + bias[o])
// 128 threads, BN=64, KC=64. Thread tile: TO(=BM/8) o-rows x 4 n.
// W stored duplicated (w,w) pairs in smem -> operands load as 64-bit packs.
// DUAL: X rows < 256 come from X0, rows >= 256 from X1 (for the concat).
template<int BM, bool DUAL>
__device__ __forceinline__ void gemm_core(
    const float* __restrict__ W, const float* __restrict__ X0,
    const float* __restrict__ X1, const float* __restrict__ bias,
    float* __restrict__ out, int K, int ldw, bool relu)
{
    constexpr int TO = BM / 8;
    constexpr int WS = BM * 2 + 4;   // dup'd W row stride (floats), mult of 4
    const int n0  = blockIdx.x * 64;
    const int o0  = blockIdx.y * BM;
    const int tid = threadIdx.x;
    const int nI  = tid & 15;        // 4-float n group
    const int oI  = tid >> 4;        // 0..7 -> TO o-rows each

    __shared__ __align__(16) float sW[64 * WS];
    __shared__ __align__(16) float sX[64 * 68];

    ull acc[TO][2] = {};

    for (int k0 = 0; k0 < K; k0 += 64) {
        __syncthreads();
        {   // W tile, duplicated: sW[k][2o..2o+1] = (w,w); coalesced over k
            const int kk = tid & 63, ob = tid >> 6;
            #pragma unroll
            for (int o = ob; o < BM; o += 2) {
                float v = W[(o0 + o) * ldw + k0 + kk];
                *(ull*)&sW[kk * WS + o * 2] = pack2(v, v);
            }
        }
        {   // X tile: [k][n], float4 coalesced
            const int f4 = tid & 15, kr = tid >> 4;
            #pragma unroll
            for (int i = 0; i < 8; i++) {
                int k = kr + i * 8;
                int c = k0 + k;
                const float* p = (!DUAL || c < 256) ? (X0 + c * 512)
                                                    : (X1 + (c - 256) * 512);
                float4 v = *(const float4*)(p + n0 + f4 * 4);
                *(float4*)&sX[k * 68 + f4 * 4] = v;
            }
        }
        __syncthreads();
        #pragma unroll 8
        for (int k = 0; k < 64; k++) {
            ulonglong2 xv = *(const ulonglong2*)&sX[k * 68 + nI * 4];
            #pragma unroll
            for (int jj = 0; jj < TO / 2; jj++) {
                ulonglong2 wv = *(const ulonglong2*)&sW[k * WS + (oI * TO + jj * 2) * 2];
                acc[jj*2  ][0] = fma2(wv.x, xv.x, acc[jj*2  ][0]);
                acc[jj*2  ][1] = fma2(wv.x, xv.y, acc[jj*2  ][1]);
                acc[jj*2+1][0] = fma2(wv.y, xv.x, acc[jj*2+1][0]);
                acc[jj*2+1][1] = fma2(wv.y, xv.y, acc[jj*2+1][1]);
            }
        }
    }

    #pragma unroll
    for (int j = 0; j < TO; j++) {
        int o = o0 + oI * TO + j;
        float b = bias ? bias[o] : 0.f;
        float2 lo = unpack2(acc[j][0]), hi = unpack2(acc[j][1]);
        float4 v = make_float4(lo.x + b, lo.y + b, hi.x + b, hi.y + b);
        if (relu) {
            v.x = fmaxf(v.x, 0.f); v.y = fmaxf(v.y, 0.f);
            v.z = fmaxf(v.z, 0.f); v.w = fmaxf(v.w, 0.f);
        }
        *(float4*)&out[o * 512 + n0 + nI * 4] = v;
    }
}

// ---------------- stage kernels ----------------

// aq = w1[:, :D] @ q + b1 ; ak = w1[:, D:] @ src     grid (8, 8, 2), 128 thr
__global__ void k_qk(const float* __restrict__ w1, const float* __restrict__ x,
                     const float* __restrict__ src, const float* __restrict__ b1)
{
    if (blockIdx.z == 0)
        gemm_core<32, false>(w1,       x,   nullptr, b1,      g_aq, 256, 512, false);
    else
        gemm_core<32, false>(w1 + 256, src, nullptr, nullptr, g_ak, 256, 512, false);
}

// scores[n][m] = sum_d w2[d]*relu(aq[d][n]+ak[d][m]) + b2
// identity: w*relu(s) = (0.5w)*(s+|s|), all packed f32x2.  grid (8,16), 128 thr
__global__ void k_score(const float* __restrict__ w2, const float* __restrict__ b2,
                        float* __restrict__ scores)
{
    const int m0  = blockIdx.x * 64;
    const int n0  = blockIdx.y * 32;
    const int tid = threadIdx.x;
    const int mI  = tid & 15;     // 4 m (2 pairs)
    const int nG  = tid >> 4;     // 4 n rows: nG*4..+3

    __shared__ __align__(16) float sA[64 * 68]; // dup'd aq: [d][2n]
    __shared__ __align__(16) float sB[64 * 68]; // ak: [d][m]
    __shared__ ull sWd[64];
    const ull MASK = 0x7fffffff7fffffffULL;

    ull acc[4][2] = {};

    for (int d0 = 0; d0 < 256; d0 += 64) {
        __syncthreads();
        {   // aq tile, duplicated, coalesced over n
            const int ln = tid & 31, dr = tid >> 5;
            #pragma unroll
            for (int d = dr; d < 64; d += 4) {
                float v = g_aq[(d0 + d) * 512 + n0 + ln];
                *(ull*)&sA[d * 68 + ln * 2] = pack2(v, v);
            }
        }
        {   // ak tile, float4 coalesced
            const int f4 = tid & 15, kr = tid >> 4;
            #pragma unroll
            for (int i = 0; i < 8; i++) {
                int d = kr + i * 8;
                float4 v = *(const float4*)&g_ak[(d0 + d) * 512 + m0 + f4 * 4];
                *(float4*)&sB[d * 68 + f4 * 4] = v;
            }
        }
        if (tid < 64) { float v = 0.5f * w2[d0 + tid]; sWd[tid] = pack2(v, v); }
        __syncthreads();
        #pragma unroll 4
        for (int d = 0; d < 64; d++) {
            ulonglong2 aA = *(const ulonglong2*)&sA[d * 68 + nG * 8];
            ulonglong2 aB = *(const ulonglong2*)&sA[d * 68 + nG * 8 + 4];
            ulonglong2 bv = *(const ulonglong2*)&sB[d * 68 + mI * 4];
            ull wd = sWd[d];
            ull av[4] = {aA.x, aA.y, aB.x, aB.y};
            #pragma unroll
            for (int j = 0; j < 4; j++) {
                ull s0 = add2(av[j], bv.x);
                ull u0 = add2(s0, s0 & MASK);
                acc[j][0] = fma2(wd, u0, acc[j][0]);
                ull s1 = add2(av[j], bv.y);
                ull u1 = add2(s1, s1 & MASK);
                acc[j][1] = fma2(wd, u1, acc[j][1]);
            }
        }
    }
    const float bs = b2[0];
    #pragma unroll
    for (int j = 0; j < 4; j++) {
        int n = n0 + nG * 4 + j;
        float2 lo = unpack2(acc[j][0]), hi = unpack2(acc[j][1]);
        float4 v = make_float4(lo.x + bs, lo.y + bs, hi.x + bs, hi.y + bs);
        *(float4*)&scores[n * 512 + m0 + mI * 4] = v;
    }
}

// softmax over m per row n, writing TRANSPOSED prob: g_probT[m][n]
// grid 128 blocks x 128 thr; block handles 4 rows (1 warp each)
__global__ void k_softmaxT(const float* __restrict__ scores)
{
    const int n0   = blockIdx.x * 4;
    const int tid  = threadIdx.x;
    const int lane = tid & 31, w = tid >> 5;
    __shared__ float sP[4][513];

    const float* row = scores + (n0 + w) * 512;
    float v[16];
    float mx = -1e30f;
    #pragma unroll
    for (int i = 0; i < 16; i++) { v[i] = row[lane + 32 * i]; mx = fmaxf(mx, v[i]); }
    #pragma unroll
    for (int o = 16; o; o >>= 1) mx = fmaxf(mx, __shfl_xor_sync(0xffffffffu, mx, o));
    float s = 0.f;
    #pragma unroll
    for (int i = 0; i < 16; i++) { v[i] = __expf(v[i] - mx); s += v[i]; }
    #pragma unroll
    for (int o = 16; o; o >>= 1) s += __shfl_xor_sync(0xffffffffu, s, o);
    float inv = 1.f / s;
    #pragma unroll
    for (int i = 0; i < 16; i++) sP[w][lane + 32 * i] = v[i] * inv;
    __syncthreads();
    #pragma unroll
    for (int i = 0; i < 4; i++) {
        int m = tid + 128 * i;
        float4 t = make_float4(sP[0][m], sP[1][m], sP[2][m], sP[3][m]);
        *(float4*)&g_probT[m * 512 + n0] = t;
    }
}

// message[d][n] = sum_m src[d][m] * probT[m][n]      grid (8,16), 128 thr
__global__ void k_msg(const float* __restrict__ src)
{
    gemm_core<16, false>(src, g_probT, nullptr, nullptr, g_msg, 512, 512, false);
}

// h2 = relu(wa @ [x; msg] + ba)                      grid (8,16), 128 thr
__global__ void k_h2(const float* __restrict__ wa, const float* __restrict__ x,
                     const float* __restrict__ ba)
{
    gemm_core<32, true>(wa, x, g_msg, ba, g_h2, 512, 512, true);
}

// y = wb @ h2 + bb                                   grid (8,16), 128 thr
__global__ void k_y(const float* __restrict__ wb, const float* __restrict__ bb,
                    float* __restrict__ y)
{
    gemm_core<16, false>(wb, g_h2, nullptr, bb, y, 512, 512, false);
}

// ---------------- launch ----------------
extern "C" void kernel_launch(void* const* d_in, const int* in_sizes, int n_in,
                              void* d_out, int out_size)
{
    const float* x   = (const float*)d_in[0];
    const float* src = (const float*)d_in[1];
    const float* w1  = (const float*)d_in[2];
    const float* b1  = (const float*)d_in[3];
    const float* w2  = (const float*)d_in[4];
    const float* b2  = (const float*)d_in[5];
    const float* wa  = (const float*)d_in[6];
    const float* ba  = (const float*)d_in[7];
    const float* wb  = (const float*)d_in[8];
    const float* bb  = (const float*)d_in[9];

    float* y      = (float*)d_out;   // (1, D, NQ)
    float* scores = y + D * NQ;      // (1, NQ, NK)

    k_qk      <<<dim3(8, 8, 2), 128>>>(w1, x, src, b1);
    k_score   <<<dim3(8, 16),   128>>>(w2, b2, scores);
    k_softmaxT<<<128,           128>>>(scores);
    k_msg     <<<dim3(8, 16),   128>>>(src);
    k_h2      <<<dim3(8, 16),   128>>>(wa, x, ba);
    k_y       <<<dim3(8, 16),   128>>>(wb, bb, y);
}

// round 3
// speedup vs baseline: 1.6736x; 1.6736x over previous
#include <cuda_runtime.h>
#include <math.h>

#define D   256
#define NQ  512
#define NK  512

// ---------------- scratch ----------------
__device__ __align__(16) float g_aq[D * NQ];      // (d, n)
__device__ __align__(16) float g_ak[D * NK];      // (d, m)
__device__ __align__(16) float g_probT[NK * NQ];  // (m, n)  transposed prob
__device__ __align__(16) float g_msg[D * NQ];     // (d, n)
__device__ __align__(16) float g_h2[2 * D * NQ];  // (o, n)

// ---------------- double-buffered 32x32-tile SGEMM core ----------------
// out[o0..o0+BM-1][n0..n0+31] = act(sum_k W[o][k]*X[k][n] + bias[o])
// 128 threads. BK=32, BN=32. All matrices have row stride 512.
// DUAL: X rows < 256 from X0, rows >= 256 from X1 (concat without materializing).
template<int BM, bool DUAL>
__device__ __forceinline__ void gemm_core(
    const float* __restrict__ W, const float* __restrict__ X0,
    const float* __restrict__ X1, const float* __restrict__ bias,
    float* __restrict__ out, int K, bool relu)
{
    constexpr int TO = BM / 16;          // o-rows per thread (1 or 2)
    const int n0  = blockIdx.x * 32;
    const int o0  = blockIdx.y * BM;
    const int tid = threadIdx.x;
    const int nI  = tid & 7;             // float4 n group
    const int oI  = tid >> 3;            // 0..15

    __shared__ float sW[2][32 * 33];     // [k][o] padded
    __shared__ float sX[2][32 * 36];     // [k][n] padded

    const int lk = tid & 31;             // inner (coalesced) index
    const int lo = tid >> 5;             // 0..3

    float rW[BM / 4], rX[8];
    float4 acc[TO];
    #pragma unroll
    for (int j = 0; j < TO; j++) acc[j] = make_float4(0.f, 0.f, 0.f, 0.f);

    const int NIT = K / 32;

    // prologue: tile 0
    #pragma unroll
    for (int p = 0; p < BM / 4; p++)
        rW[p] = __ldg(&W[(o0 + lo + p * 4) * 512 + lk]);
    {
        const float* Xb = (!DUAL) ? X0 : X0;   // k0 = 0 always side 0
        #pragma unroll
        for (int p = 0; p < 8; p++)
            rX[p] = __ldg(&Xb[(lo + p * 4) * 512 + n0 + lk]);
    }
    #pragma unroll
    for (int p = 0; p < BM / 4; p++) sW[0][lk * 33 + lo + p * 4] = rW[p];
    #pragma unroll
    for (int p = 0; p < 8; p++)      sX[0][(lo + p * 4) * 36 + lk] = rX[p];
    __syncthreads();

    for (int it = 0; it < NIT; it++) {
        const int cur = it & 1;
        if (it + 1 < NIT) {              // register prefetch of next tile
            const int k0 = (it + 1) * 32;
            #pragma unroll
            for (int p = 0; p < BM / 4; p++)
                rW[p] = __ldg(&W[(o0 + lo + p * 4) * 512 + k0 + lk]);
            const float* Xb = (!DUAL || k0 < 256) ? X0 + k0 * 512
                                                  : X1 + (k0 - 256) * 512;
            #pragma unroll
            for (int p = 0; p < 8; p++)
                rX[p] = __ldg(&Xb[(lo + p * 4) * 512 + n0 + lk]);
        }
        #pragma unroll
        for (int k = 0; k < 32; k++) {
            float4 xv = *(const float4*)&sX[cur][k * 36 + nI * 4];
            #pragma unroll
            for (int j = 0; j < TO; j++) {
                float w = sW[cur][k * 33 + oI * TO + j];
                acc[j].x += w * xv.x; acc[j].y += w * xv.y;
                acc[j].z += w * xv.z; acc[j].w += w * xv.w;
            }
        }
        if (it + 1 < NIT) {
            #pragma unroll
            for (int p = 0; p < BM / 4; p++) sW[cur ^ 1][lk * 33 + lo + p * 4] = rW[p];
            #pragma unroll
            for (int p = 0; p < 8; p++)      sX[cur ^ 1][(lo + p * 4) * 36 + lk] = rX[p];
            __syncthreads();
        }
    }

    #pragma unroll
    for (int j = 0; j < TO; j++) {
        const int o = o0 + oI * TO + j;
        const float b = bias ? bias[o] : 0.f;
        float4 v = acc[j];
        v.x += b; v.y += b; v.z += b; v.w += b;
        if (relu) {
            v.x = fmaxf(v.x, 0.f); v.y = fmaxf(v.y, 0.f);
            v.z = fmaxf(v.z, 0.f); v.w = fmaxf(v.w, 0.f);
        }
        *(float4*)&out[o * 512 + n0 + nI * 4] = v;
    }
}

// ---------------- stage kernels ----------------

// aq = w1[:, :D] @ q + b1 ; ak = w1[:, D:] @ src     grid (16, 8, 2), 128 thr
__global__ void __launch_bounds__(128) k_qk(
    const float* __restrict__ w1, const float* __restrict__ x,
    const float* __restrict__ src, const float* __restrict__ b1)
{
    if (blockIdx.z == 0)
        gemm_core<32, false>(w1,       x,   nullptr, b1,      g_aq, 256, false);
    else
        gemm_core<32, false>(w1 + 256, src, nullptr, nullptr, g_ak, 256, false);
}

// scores[n][m] = sum_d w2[d]*relu(aq[d][n]+ak[d][m]) + b2    grid (16,16), 128 thr
__global__ void __launch_bounds__(128) k_score(
    const float* __restrict__ w2, const float* __restrict__ b2,
    float* __restrict__ scores)
{
    const int m0  = blockIdx.x * 32;
    const int n0  = blockIdx.y * 32;
    const int tid = threadIdx.x;
    const int mI  = tid & 7;      // float4 over m
    const int nG  = tid >> 3;     // 0..15 -> 2 n rows

    __shared__ float sA[2][32 * 33];  // [d][n]
    __shared__ float sB[2][32 * 36];  // [d][m]
    __shared__ float sw[2][32];

    const int lc = tid & 31, lr = tid >> 5;

    float rA[8], rB[8];
    float4 acc0 = make_float4(0.f, 0.f, 0.f, 0.f);
    float4 acc1 = make_float4(0.f, 0.f, 0.f, 0.f);

    // prologue
    #pragma unroll
    for (int p = 0; p < 8; p++) {
        rA[p] = __ldg(&g_aq[(lr + p * 4) * 512 + n0 + lc]);
        rB[p] = __ldg(&g_ak[(lr + p * 4) * 512 + m0 + lc]);
    }
    #pragma unroll
    for (int p = 0; p < 8; p++) {
        sA[0][(lr + p * 4) * 33 + lc] = rA[p];
        sB[0][(lr + p * 4) * 36 + lc] = rB[p];
    }
    if (tid < 32) sw[0][tid] = __ldg(&w2[tid]);
    __syncthreads();

    for (int it = 0; it < 8; it++) {
        const int cur = it & 1;
        if (it + 1 < 8) {
            const int d0 = (it + 1) * 32;
            #pragma unroll
            for (int p = 0; p < 8; p++) {
                rA[p] = __ldg(&g_aq[(d0 + lr + p * 4) * 512 + n0 + lc]);
                rB[p] = __ldg(&g_ak[(d0 + lr + p * 4) * 512 + m0 + lc]);
            }
        }
        #pragma unroll
        for (int d = 0; d < 32; d++) {
            float4 bv = *(const float4*)&sB[cur][d * 36 + mI * 4];
            float a0 = sA[cur][d * 33 + nG * 2];
            float a1 = sA[cur][d * 33 + nG * 2 + 1];
            float w  = sw[cur][d];
            acc0.x += w * fmaxf(a0 + bv.x, 0.f);
            acc0.y += w * fmaxf(a0 + bv.y, 0.f);
            acc0.z += w * fmaxf(a0 + bv.z, 0.f);
            acc0.w += w * fmaxf(a0 + bv.w, 0.f);
            acc1.x += w * fmaxf(a1 + bv.x, 0.f);
            acc1.y += w * fmaxf(a1 + bv.y, 0.f);
            acc1.z += w * fmaxf(a1 + bv.z, 0.f);
            acc1.w += w * fmaxf(a1 + bv.w, 0.f);
        }
        if (it + 1 < 8) {
            #pragma unroll
            for (int p = 0; p < 8; p++) {
                sA[cur ^ 1][(lr + p * 4) * 33 + lc] = rA[p];
                sB[cur ^ 1][(lr + p * 4) * 36 + lc] = rB[p];
            }
            if (tid < 32) sw[cur ^ 1][tid] = __ldg(&w2[(it + 1) * 32 + tid]);
            __syncthreads();
        }
    }

    const float bs = b2[0];
    acc0.x += bs; acc0.y += bs; acc0.z += bs; acc0.w += bs;
    acc1.x += bs; acc1.y += bs; acc1.z += bs; acc1.w += bs;
    const int na = n0 + nG * 2;
    *(float4*)&scores[na * 512 + m0 + mI * 4]       = acc0;
    *(float4*)&scores[(na + 1) * 512 + m0 + mI * 4] = acc1;
}

// softmax over m per row n, writing TRANSPOSED prob: g_probT[m][n]
// grid 128 x 128 thr; block handles 4 rows (1 warp each)
__global__ void __launch_bounds__(128) k_softmaxT(const float* __restrict__ scores)
{
    const int n0   = blockIdx.x * 4;
    const int tid  = threadIdx.x;
    const int lane = tid & 31, w = tid >> 5;
    __shared__ float sP[4][513];

    const float* row = scores + (n0 + w) * 512;
    float v[16];
    float mx = -1e30f;
    #pragma unroll
    for (int i = 0; i < 16; i++) { v[i] = row[lane + 32 * i]; mx = fmaxf(mx, v[i]); }
    #pragma unroll
    for (int o = 16; o; o >>= 1) mx = fmaxf(mx, __shfl_xor_sync(0xffffffffu, mx, o));
    float s = 0.f;
    #pragma unroll
    for (int i = 0; i < 16; i++) { v[i] = __expf(v[i] - mx); s += v[i]; }
    #pragma unroll
    for (int o = 16; o; o >>= 1) s += __shfl_xor_sync(0xffffffffu, s, o);
    float inv = 1.f / s;
    #pragma unroll
    for (int i = 0; i < 16; i++) sP[w][lane + 32 * i] = v[i] * inv;
    __syncthreads();
    #pragma unroll
    for (int i = 0; i < 4; i++) {
        int m = tid + 128 * i;
        float4 t = make_float4(sP[0][m], sP[1][m], sP[2][m], sP[3][m]);
        *(float4*)&g_probT[m * 512 + n0] = t;
    }
}

// message[d][n] = sum_m src[d][m] * probT[m][n]      grid (16,16), 128 thr
__global__ void __launch_bounds__(128) k_msg(const float* __restrict__ src)
{
    gemm_core<16, false>(src, g_probT, nullptr, nullptr, g_msg, 512, false);
}

// h2 = relu(wa @ [x; msg] + ba)                      grid (16,16), 128 thr
__global__ void __launch_bounds__(128) k_h2(
    const float* __restrict__ wa, const float* __restrict__ x,
    const float* __restrict__ ba)
{
    gemm_core<32, true>(wa, x, g_msg, ba, g_h2, 512, true);
}

// y = wb @ h2 + bb                                   grid (16,16), 128 thr
__global__ void __launch_bounds__(128) k_y(
    const float* __restrict__ wb, const float* __restrict__ bb,
    float* __restrict__ y)
{
    gemm_core<16, false>(wb, g_h2, nullptr, bb, y, 512, false);
}

// ---------------- launch ----------------
extern "C" void kernel_launch(void* const* d_in, const int* in_sizes, int n_in,
                              void* d_out, int out_size)
{
    const float* x   = (const float*)d_in[0];
    const float* src = (const float*)d_in[1];
    const float* w1  = (const float*)d_in[2];
    const float* b1  = (const float*)d_in[3];
    const float* w2  = (const float*)d_in[4];
    const float* b2  = (const float*)d_in[5];
    const float* wa  = (const float*)d_in[6];
    const float* ba  = (const float*)d_in[7];
    const float* wb  = (const float*)d_in[8];
    const float* bb  = (const float*)d_in[9];

    float* y      = (float*)d_out;   // (1, D, NQ)
    float* scores = y + D * NQ;      // (1, NQ, NK)

    k_qk      <<<dim3(16, 8, 2), 128>>>(w1, x, src, b1);
    k_score   <<<dim3(16, 16),   128>>>(w2, b2, scores);
    k_softmaxT<<<128,            128>>>(scores);
    k_msg     <<<dim3(16, 16),   128>>>(src);
    k_h2      <<<dim3(16, 16),   128>>>(wa, x, ba);
    k_y       <<<dim3(16, 16),   128>>>(wb, bb, y);
}

// round 4
// speedup vs baseline: 1.8623x; 1.1127x over previous
#include <cuda_runtime.h>
#include <math.h>

#define D   256
#define NQ  512
#define NK  512

// ---------------- scratch ----------------
__device__ __align__(16) float g_aq[D * NQ];      // (d, n)
__device__ __align__(16) float g_ak[D * NK];      // (d, m)
__device__ __align__(16) float g_probT[NK * NQ];  // (m, n)
__device__ __align__(16) float g_msg[D * NQ];     // (d, n)
__device__ __align__(16) float g_h2[2 * D * NQ];  // (o, n)

// ---------------- double-buffered SGEMM core, tile BM x 64, 128 threads ----
// out[o0..o0+BM-1][n0..n0+63] = act(sum_k W[o][k]*X[k][n] + bias[o])
// Thread tile: TO = BM/8 o-rows x 4 n  (BM=32 -> 4x4, BM=16 -> 2x4).
// All row strides are 512. DUAL: X rows <256 from X0, >=256 from X1.
template<int BM, bool DUAL>
__device__ __forceinline__ void gemm_core(
    const float* __restrict__ W, const float* __restrict__ X0,
    const float* __restrict__ X1, const float* __restrict__ bias,
    float* __restrict__ out, int K, bool relu)
{
    constexpr int TO = BM / 8;           // o per thread
    constexpr int WS = BM + 4;           // sW row stride
    constexpr int NW = BM / 16;          // W float4 loads per thread (2 or 1)
    const int n0  = blockIdx.x * 64;
    const int o0  = blockIdx.y * BM;
    const int tid = threadIdx.x;
    const int nI  = tid & 15;            // float4 n group (64 n)
    const int oG  = tid >> 4;            // 0..7 -> TO o-rows

    __shared__ __align__(16) float sW[2][32 * WS];  // [k][o]
    __shared__ __align__(16) float sX[2][32 * 68];  // [k][n]

    // loader indices
    const int wo  = (BM == 32) ? (tid >> 2) : (tid >> 3);   // W o-row
    const int wf  = (BM == 32) ? (tid & 3)  : (tid & 7);    // W f4 base
    const int xn4 = tid & 15;            // X float4 col
    const int xkr = tid >> 4;            // X row base (0..7)

    float4 rw[NW], rx[4];
    float4 acc[TO];
    #pragma unroll
    for (int j = 0; j < TO; j++) acc[j] = make_float4(0.f, 0.f, 0.f, 0.f);

    const int NIT = K / 32;

    // ---- prologue: tile 0 into regs, then smem buf 0
    #pragma unroll
    for (int p = 0; p < NW; p++)
        rw[p] = *(const float4*)&W[(o0 + wo) * 512 + (wf + p * 4) * 4];
    #pragma unroll
    for (int p = 0; p < 4; p++)
        rx[p] = *(const float4*)&X0[(xkr + p * 8) * 512 + n0 + xn4 * 4];
    #pragma unroll
    for (int p = 0; p < NW; p++) {
        const int f4 = wf + p * 4;
        sW[0][(f4 * 4 + 0) * WS + wo] = rw[p].x;
        sW[0][(f4 * 4 + 1) * WS + wo] = rw[p].y;
        sW[0][(f4 * 4 + 2) * WS + wo] = rw[p].z;
        sW[0][(f4 * 4 + 3) * WS + wo] = rw[p].w;
    }
    #pragma unroll
    for (int p = 0; p < 4; p++)
        *(float4*)&sX[0][(xkr + p * 8) * 68 + xn4 * 4] = rx[p];
    __syncthreads();

    for (int it = 0; it < NIT; it++) {
        const int cur = it & 1;
        if (it + 1 < NIT) {
            const int k0 = (it + 1) * 32;
            #pragma unroll
            for (int p = 0; p < NW; p++)
                rw[p] = *(const float4*)&W[(o0 + wo) * 512 + k0 + (wf + p * 4) * 4];
            const float* Xb = (!DUAL || k0 < 256) ? X0 + k0 * 512
                                                  : X1 + (k0 - 256) * 512;
            #pragma unroll
            for (int p = 0; p < 4; p++)
                rx[p] = *(const float4*)&Xb[(xkr + p * 8) * 512 + n0 + xn4 * 4];
        }
        #pragma unroll
        for (int k = 0; k < 32; k++) {
            float4 xv = *(const float4*)&sX[cur][k * 68 + nI * 4];
            if (TO == 4) {
                float4 wv = *(const float4*)&sW[cur][k * WS + oG * 4];
                acc[0].x += wv.x * xv.x; acc[0].y += wv.x * xv.y;
                acc[0].z += wv.x * xv.z; acc[0].w += wv.x * xv.w;
                acc[1].x += wv.y * xv.x; acc[1].y += wv.y * xv.y;
                acc[1].z += wv.y * xv.z; acc[1].w += wv.y * xv.w;
                acc[2].x += wv.z * xv.x; acc[2].y += wv.z * xv.y;
                acc[2].z += wv.z * xv.z; acc[2].w += wv.z * xv.w;
                acc[3].x += wv.w * xv.x; acc[3].y += wv.w * xv.y;
                acc[3].z += wv.w * xv.z; acc[3].w += wv.w * xv.w;
            } else {
                float2 wv = *(const float2*)&sW[cur][k * WS + oG * 2];
                acc[0].x += wv.x * xv.x; acc[0].y += wv.x * xv.y;
                acc[0].z += wv.x * xv.z; acc[0].w += wv.x * xv.w;
                acc[1].x += wv.y * xv.x; acc[1].y += wv.y * xv.y;
                acc[1].z += wv.y * xv.z; acc[1].w += wv.y * xv.w;
            }
        }
        if (it + 1 < NIT) {
            const int nb = cur ^ 1;
            #pragma unroll
            for (int p = 0; p < NW; p++) {
                const int f4 = wf + p * 4;
                sW[nb][(f4 * 4 + 0) * WS + wo] = rw[p].x;
                sW[nb][(f4 * 4 + 1) * WS + wo] = rw[p].y;
                sW[nb][(f4 * 4 + 2) * WS + wo] = rw[p].z;
                sW[nb][(f4 * 4 + 3) * WS + wo] = rw[p].w;
            }
            #pragma unroll
            for (int p = 0; p < 4; p++)
                *(float4*)&sX[nb][(xkr + p * 8) * 68 + xn4 * 4] = rx[p];
            __syncthreads();
        }
    }

    #pragma unroll
    for (int j = 0; j < TO; j++) {
        const int o = o0 + oG * TO + j;
        const float b = bias ? bias[o] : 0.f;
        float4 v = acc[j];
        v.x += b; v.y += b; v.z += b; v.w += b;
        if (relu) {
            v.x = fmaxf(v.x, 0.f); v.y = fmaxf(v.y, 0.f);
            v.z = fmaxf(v.z, 0.f); v.w = fmaxf(v.w, 0.f);
        }
        *(float4*)&out[o * 512 + n0 + nI * 4] = v;
    }
}

// ---------------- stage kernels ----------------

// aq = w1[:, :D] @ x + b1 ; ak = w1[:, D:] @ src     grid (8, 8, 2), 128 thr
__global__ void __launch_bounds__(128) k_qk(
    const float* __restrict__ w1, const float* __restrict__ x,
    const float* __restrict__ src, const float* __restrict__ b1)
{
    if (blockIdx.z == 0)
        gemm_core<32, false>(w1,       x,   nullptr, b1,      g_aq, 256, false);
    else
        gemm_core<32, false>(w1 + 256, src, nullptr, nullptr, g_ak, 256, false);
}

// scores[n][m] = sum_d w2[d]*relu(aq[d][n]+ak[d][m]) + b2    grid (8,16), 128 thr
// block tile: 32 n x 64 m; thread tile 4n x 4m
__global__ void __launch_bounds__(128) k_score(
    const float* __restrict__ w2, const float* __restrict__ b2,
    float* __restrict__ scores)
{
    const int m0  = blockIdx.x * 64;
    const int n0  = blockIdx.y * 32;
    const int tid = threadIdx.x;
    const int mI  = tid & 15;     // float4 m
    const int nG  = tid >> 4;     // 0..7 -> 4 n rows

    __shared__ __align__(16) float sA[2][32 * 36]; // [d][n]
    __shared__ __align__(16) float sB[2][32 * 68]; // [d][m]
    __shared__ float sw[2][32];

    const int an4 = tid & 7,  adr = tid >> 3;   // A loader
    const int bm4 = tid & 15, bdr = tid >> 4;   // B loader

    float4 ra[2], rb[4];
    float rwv;
    float4 acc[4];
    #pragma unroll
    for (int j = 0; j < 4; j++) acc[j] = make_float4(0.f, 0.f, 0.f, 0.f);

    // prologue
    #pragma unroll
    for (int p = 0; p < 2; p++)
        ra[p] = *(const float4*)&g_aq[(adr + p * 16) * 512 + n0 + an4 * 4];
    #pragma unroll
    for (int p = 0; p < 4; p++)
        rb[p] = *(const float4*)&g_ak[(bdr + p * 8) * 512 + m0 + bm4 * 4];
    rwv = (tid < 32) ? w2[tid] : 0.f;
    #pragma unroll
    for (int p = 0; p < 2; p++)
        *(float4*)&sA[0][(adr + p * 16) * 36 + an4 * 4] = ra[p];
    #pragma unroll
    for (int p = 0; p < 4; p++)
        *(float4*)&sB[0][(bdr + p * 8) * 68 + bm4 * 4] = rb[p];
    if (tid < 32) sw[0][tid] = rwv;
    __syncthreads();

    for (int it = 0; it < 8; it++) {
        const int cur = it & 1;
        if (it + 1 < 8) {
            const int d0 = (it + 1) * 32;
            #pragma unroll
            for (int p = 0; p < 2; p++)
                ra[p] = *(const float4*)&g_aq[(d0 + adr + p * 16) * 512 + n0 + an4 * 4];
            #pragma unroll
            for (int p = 0; p < 4; p++)
                rb[p] = *(const float4*)&g_ak[(d0 + bdr + p * 8) * 512 + m0 + bm4 * 4];
            if (tid < 32) rwv = w2[d0 + tid];
        }
        #pragma unroll
        for (int d = 0; d < 32; d++) {
            float4 av = *(const float4*)&sA[cur][d * 36 + nG * 4];
            float4 bv = *(const float4*)&sB[cur][d * 68 + mI * 4];
            float w  = sw[cur][d];
            float a[4] = {av.x, av.y, av.z, av.w};
            #pragma unroll
            for (int j = 0; j < 4; j++) {
                acc[j].x += w * fmaxf(a[j] + bv.x, 0.f);
                acc[j].y += w * fmaxf(a[j] + bv.y, 0.f);
                acc[j].z += w * fmaxf(a[j] + bv.z, 0.f);
                acc[j].w += w * fmaxf(a[j] + bv.w, 0.f);
            }
        }
        if (it + 1 < 8) {
            const int nb = cur ^ 1;
            #pragma unroll
            for (int p = 0; p < 2; p++)
                *(float4*)&sA[nb][(adr + p * 16) * 36 + an4 * 4] = ra[p];
            #pragma unroll
            for (int p = 0; p < 4; p++)
                *(float4*)&sB[nb][(bdr + p * 8) * 68 + bm4 * 4] = rb[p];
            if (tid < 32) sw[nb][tid] = rwv;
            __syncthreads();
        }
    }

    const float bs = b2[0];
    #pragma unroll
    for (int j = 0; j < 4; j++) {
        const int n = n0 + nG * 4 + j;
        float4 v = acc[j];
        v.x += bs; v.y += bs; v.z += bs; v.w += bs;
        *(float4*)&scores[n * 512 + m0 + mI * 4] = v;
    }
}

// softmax over m per row n, writing TRANSPOSED prob: g_probT[m][n]
__global__ void __launch_bounds__(128) k_softmaxT(const float* __restrict__ scores)
{
    const int n0   = blockIdx.x * 4;
    const int tid  = threadIdx.x;
    const int lane = tid & 31, w = tid >> 5;
    __shared__ float sP[4][513];

    const float* row = scores + (n0 + w) * 512;
    float v[16];
    float mx = -1e30f;
    #pragma unroll
    for (int i = 0; i < 16; i++) { v[i] = row[lane + 32 * i]; mx = fmaxf(mx, v[i]); }
    #pragma unroll
    for (int o = 16; o; o >>= 1) mx = fmaxf(mx, __shfl_xor_sync(0xffffffffu, mx, o));
    float s = 0.f;
    #pragma unroll
    for (int i = 0; i < 16; i++) { v[i] = __expf(v[i] - mx); s += v[i]; }
    #pragma unroll
    for (int o = 16; o; o >>= 1) s += __shfl_xor_sync(0xffffffffu, s, o);
    float inv = 1.f / s;
    #pragma unroll
    for (int i = 0; i < 16; i++) sP[w][lane + 32 * i] = v[i] * inv;
    __syncthreads();
    #pragma unroll
    for (int i = 0; i < 4; i++) {
        int m = tid + 128 * i;
        float4 t = make_float4(sP[0][m], sP[1][m], sP[2][m], sP[3][m]);
        *(float4*)&g_probT[m * 512 + n0] = t;
    }
}

// message[d][n] = sum_m src[d][m] * probT[m][n]      grid (8,16), 128 thr
__global__ void __launch_bounds__(128) k_msg(const float* __restrict__ src)
{
    gemm_core<16, false>(src, g_probT, nullptr, nullptr, g_msg, 512, false);
}

// h2 = relu(wa @ [x; msg] + ba)                      grid (8,16), 128 thr
__global__ void __launch_bounds__(128) k_h2(
    const float* __restrict__ wa, const float* __restrict__ x,
    const float* __restrict__ ba)
{
    gemm_core<32, true>(wa, x, g_msg, ba, g_h2, 512, true);
}

// y = wb @ h2 + bb                                   grid (8,16), 128 thr
__global__ void __launch_bounds__(128) k_y(
    const float* __restrict__ wb, const float* __restrict__ bb,
    float* __restrict__ y)
{
    gemm_core<16, false>(wb, g_h2, nullptr, bb, y, 512, false);
}

// ---------------- launch ----------------
extern "C" void kernel_launch(void* const* d_in, const int* in_sizes, int n_in,
                              void* d_out, int out_size)
{
    const float* x   = (const float*)d_in[0];
    const float* src = (const float*)d_in[1];
    const float* w1  = (const float*)d_in[2];
    const float* b1  = (const float*)d_in[3];
    const float* w2  = (const float*)d_in[4];
    const float* b2  = (const float*)d_in[5];
    const float* wa  = (const float*)d_in[6];
    const float* ba  = (const float*)d_in[7];
    const float* wb  = (const float*)d_in[8];
    const float* bb  = (const float*)d_in[9];

    float* y      = (float*)d_out;   // (1, D, NQ)
    float* scores = y + D * NQ;      // (1, NQ, NK)

    k_qk      <<<dim3(8, 8, 2), 128>>>(w1, x, src, b1);
    k_score   <<<dim3(8, 16),   128>>>(w2, b2, scores);
    k_softmaxT<<<128,           128>>>(scores);
    k_msg     <<<dim3(8, 16),   128>>>(src);
    k_h2      <<<dim3(8, 16),   128>>>(wa, x, ba);
    k_y       <<<dim3(8, 16),   128>>>(wb, bb, y);
}

// round 5
// speedup vs baseline: 2.5368x; 1.3622x over previous
#include <cuda_runtime.h>
#include <math.h>

#define D   256
#define NQ  512
#define NK  512

// ---------------- scratch ----------------
__device__ __align__(16) float g_aq[D * NQ];      // (d, n)
__device__ __align__(16) float g_ak[D * NK];      // (d, m)
__device__ __align__(16) float g_probT[NK * NQ];  // (m, n)
__device__ __align__(16) float g_msg[D * NQ];     // (d, n)
__device__ __align__(16) float g_h2[2 * D * NQ];  // (o, n)

// ---------------- split-K SGEMM core: tile BM x 64, 256 threads ----------------
// Two warpgroups (128 thr each) compute the SAME output tile over half of K
// each; partials reduced through smem. Thread tile: TO=BM/8 o x 4 n.
// Single-buffered smem with register prefetch (2 barriers per k-tile).
// All row strides 512. DUAL: X rows <256 from X0, >=256 from X1.
template<int BM, bool DUAL>
__device__ __forceinline__ void gemm_core(
    const float* __restrict__ W, const float* __restrict__ X0,
    const float* __restrict__ X1, const float* __restrict__ bias,
    float* __restrict__ out, int K, bool relu)
{
    constexpr int TO = BM / 8;
    constexpr int WS = BM + 4;
    constexpr int NW = BM / 16;          // W float4 loads per thread
    const int n0  = blockIdx.x * 64;
    const int o0  = blockIdx.y * BM;
    const int tid = threadIdx.x;
    const int wg  = tid >> 7;            // warpgroup 0/1
    const int t   = tid & 127;

    const int nI  = t & 15;
    const int oG  = t >> 4;

    __shared__ __align__(16) float sW[2][32 * WS];
    __shared__ __align__(16) float sX[2][32 * 68];
    __shared__ __align__(16) float sR[128 * TO * 4];

    const int wo  = (BM == 32) ? (t >> 2) : (t >> 3);
    const int wf  = (BM == 32) ? (t & 3)  : (t & 7);
    const int xn4 = t & 15;
    const int xkr = t >> 4;

    const int kb  = wg * (K >> 1);
    const int NIT = K >> 6;              // (K/2)/32

    float4 rw[NW], rx[4];
    float4 acc[TO];
    #pragma unroll
    for (int j = 0; j < TO; j++) acc[j] = make_float4(0.f, 0.f, 0.f, 0.f);

    // prefetch tile 0
    {
        const int k0 = kb;
        #pragma unroll
        for (int p = 0; p < NW; p++)
            rw[p] = *(const float4*)&W[(o0 + wo) * 512 + k0 + (wf + p * 4) * 4];
        const float* Xb = (!DUAL || k0 < 256) ? X0 + k0 * 512
                                              : X1 + (k0 - 256) * 512;
        #pragma unroll
        for (int p = 0; p < 4; p++)
            rx[p] = *(const float4*)&Xb[(xkr + p * 8) * 512 + n0 + xn4 * 4];
    }

    for (int it = 0; it < NIT; it++) {
        __syncthreads();                 // previous compute finished
        #pragma unroll
        for (int p = 0; p < NW; p++) {
            const int f4 = wf + p * 4;
            sW[wg][(f4 * 4 + 0) * WS + wo] = rw[p].x;
            sW[wg][(f4 * 4 + 1) * WS + wo] = rw[p].y;
            sW[wg][(f4 * 4 + 2) * WS + wo] = rw[p].z;
            sW[wg][(f4 * 4 + 3) * WS + wo] = rw[p].w;
        }
        #pragma unroll
        for (int p = 0; p < 4; p++)
            *(float4*)&sX[wg][(xkr + p * 8) * 68 + xn4 * 4] = rx[p];
        __syncthreads();

        if (it + 1 < NIT) {              // prefetch next tile (overlaps compute)
            const int k0 = kb + (it + 1) * 32;
            #pragma unroll
            for (int p = 0; p < NW; p++)
                rw[p] = *(const float4*)&W[(o0 + wo) * 512 + k0 + (wf + p * 4) * 4];
            const float* Xb = (!DUAL || k0 < 256) ? X0 + k0 * 512
                                                  : X1 + (k0 - 256) * 512;
            #pragma unroll
            for (int p = 0; p < 4; p++)
                rx[p] = *(const float4*)&Xb[(xkr + p * 8) * 512 + n0 + xn4 * 4];
        }

        #pragma unroll
        for (int k = 0; k < 32; k++) {
            float4 xv = *(const float4*)&sX[wg][k * 68 + nI * 4];
            if (TO == 4) {
                float4 wv = *(const float4*)&sW[wg][k * WS + oG * 4];
                acc[0].x += wv.x * xv.x; acc[0].y += wv.x * xv.y;
                acc[0].z += wv.x * xv.z; acc[0].w += wv.x * xv.w;
                acc[1].x += wv.y * xv.x; acc[1].y += wv.y * xv.y;
                acc[1].z += wv.y * xv.z; acc[1].w += wv.y * xv.w;
                acc[2].x += wv.z * xv.x; acc[2].y += wv.z * xv.y;
                acc[2].z += wv.z * xv.z; acc[2].w += wv.z * xv.w;
                acc[3].x += wv.w * xv.x; acc[3].y += wv.w * xv.y;
                acc[3].z += wv.w * xv.z; acc[3].w += wv.w * xv.w;
            } else {
                float2 wv = *(const float2*)&sW[wg][k * WS + oG * 2];
                acc[0].x += wv.x * xv.x; acc[0].y += wv.x * xv.y;
                acc[0].z += wv.x * xv.z; acc[0].w += wv.x * xv.w;
                acc[1].x += wv.y * xv.x; acc[1].y += wv.y * xv.y;
                acc[1].z += wv.y * xv.z; acc[1].w += wv.y * xv.w;
            }
        }
    }

    // split-K reduction: wg1 stages, wg0 reduces + epilogue
    if (wg == 1) {
        #pragma unroll
        for (int j = 0; j < TO; j++)
            *(float4*)&sR[(t * TO + j) * 4] = acc[j];
    }
    __syncthreads();
    if (wg == 0) {
        #pragma unroll
        for (int j = 0; j < TO; j++) {
            float4 r = *(const float4*)&sR[(t * TO + j) * 4];
            const int o = o0 + oG * TO + j;
            const float b = bias ? bias[o] : 0.f;
            float4 v = acc[j];
            v.x += r.x + b; v.y += r.y + b; v.z += r.z + b; v.w += r.w + b;
            if (relu) {
                v.x = fmaxf(v.x, 0.f); v.y = fmaxf(v.y, 0.f);
                v.z = fmaxf(v.z, 0.f); v.w = fmaxf(v.w, 0.f);
            }
            *(float4*)&out[o * 512 + n0 + nI * 4] = v;
        }
    }
}

// ---------------- stage kernels ----------------

// aq = w1[:, :D] @ x + b1 ; ak = w1[:, D:] @ src     grid (8, 8, 2), 256 thr
__global__ void __launch_bounds__(256) k_qk(
    const float* __restrict__ w1, const float* __restrict__ x,
    const float* __restrict__ src, const float* __restrict__ b1)
{
    if (blockIdx.z == 0)
        gemm_core<32, false>(w1,       x,   nullptr, b1,      g_aq, 256, false);
    else
        gemm_core<32, false>(w1 + 256, src, nullptr, nullptr, g_ak, 256, false);
}

// scores[n][m] = sum_d w2[d]*relu(aq[d][n]+ak[d][m]) + b2    grid (8,16), 256 thr
// block tile 32 n x 64 m; two warpgroups split d (128 each); thread 4n x 4m
__global__ void __launch_bounds__(256) k_score(
    const float* __restrict__ w2, const float* __restrict__ b2,
    float* __restrict__ scores)
{
    const int m0  = blockIdx.x * 64;
    const int n0  = blockIdx.y * 32;
    const int tid = threadIdx.x;
    const int wg  = tid >> 7;
    const int t   = tid & 127;
    const int mI  = t & 15;
    const int nG  = t >> 4;

    __shared__ __align__(16) float sA[2][32 * 36];
    __shared__ __align__(16) float sB[2][32 * 68];
    __shared__ float sw[2][32];
    __shared__ __align__(16) float sR[128 * 16];

    const int an4 = t & 7,  adr = t >> 3;
    const int bm4 = t & 15, bdr = t >> 4;
    const int db  = wg * 128;

    float4 ra[2], rb[4];
    float rwv;
    float4 acc[4];
    #pragma unroll
    for (int j = 0; j < 4; j++) acc[j] = make_float4(0.f, 0.f, 0.f, 0.f);

    // prefetch d-tile 0
    #pragma unroll
    for (int p = 0; p < 2; p++)
        ra[p] = *(const float4*)&g_aq[(db + adr + p * 16) * 512 + n0 + an4 * 4];
    #pragma unroll
    for (int p = 0; p < 4; p++)
        rb[p] = *(const float4*)&g_ak[(db + bdr + p * 8) * 512 + m0 + bm4 * 4];
    rwv = (t < 32) ? w2[db + t] : 0.f;

    for (int it = 0; it < 4; it++) {
        __syncthreads();
        #pragma unroll
        for (int p = 0; p < 2; p++)
            *(float4*)&sA[wg][(adr + p * 16) * 36 + an4 * 4] = ra[p];
        #pragma unroll
        for (int p = 0; p < 4; p++)
            *(float4*)&sB[wg][(bdr + p * 8) * 68 + bm4 * 4] = rb[p];
        if (t < 32) sw[wg][t] = rwv;
        __syncthreads();

        if (it + 1 < 4) {
            const int d0 = db + (it + 1) * 32;
            #pragma unroll
            for (int p = 0; p < 2; p++)
                ra[p] = *(const float4*)&g_aq[(d0 + adr + p * 16) * 512 + n0 + an4 * 4];
            #pragma unroll
            for (int p = 0; p < 4; p++)
                rb[p] = *(const float4*)&g_ak[(d0 + bdr + p * 8) * 512 + m0 + bm4 * 4];
            if (t < 32) rwv = w2[d0 + t];
        }

        #pragma unroll
        for (int d = 0; d < 32; d++) {
            float4 av = *(const float4*)&sA[wg][d * 36 + nG * 4];
            float4 bv = *(const float4*)&sB[wg][d * 68 + mI * 4];
            float w  = sw[wg][d];
            float a[4] = {av.x, av.y, av.z, av.w};
            #pragma unroll
            for (int j = 0; j < 4; j++) {
                acc[j].x += w * fmaxf(a[j] + bv.x, 0.f);
                acc[j].y += w * fmaxf(a[j] + bv.y, 0.f);
                acc[j].z += w * fmaxf(a[j] + bv.z, 0.f);
                acc[j].w += w * fmaxf(a[j] + bv.w, 0.f);
            }
        }
    }

    if (wg == 1) {
        #pragma unroll
        for (int j = 0; j < 4; j++)
            *(float4*)&sR[(t * 4 + j) * 4] = acc[j];
    }
    __syncthreads();
    if (wg == 0) {
        const float bs = b2[0];
        #pragma unroll
        for (int j = 0; j < 4; j++) {
            float4 r = *(const float4*)&sR[(t * 4 + j) * 4];
            const int n = n0 + nG * 4 + j;
            float4 v = acc[j];
            v.x += r.x + bs; v.y += r.y + bs;
            v.z += r.z + bs; v.w += r.w + bs;
            *(float4*)&scores[n * 512 + m0 + mI * 4] = v;
        }
    }
}

// softmax over m per row n, writing TRANSPOSED prob: g_probT[m][n]
__global__ void __launch_bounds__(128) k_softmaxT(const float* __restrict__ scores)
{
    const int n0   = blockIdx.x * 4;
    const int tid  = threadIdx.x;
    const int lane = tid & 31, w = tid >> 5;
    __shared__ float sP[4][513];

    const float* row = scores + (n0 + w) * 512;
    float v[16];
    float mx = -1e30f;
    #pragma unroll
    for (int i = 0; i < 16; i++) { v[i] = row[lane + 32 * i]; mx = fmaxf(mx, v[i]); }
    #pragma unroll
    for (int o = 16; o; o >>= 1) mx = fmaxf(mx, __shfl_xor_sync(0xffffffffu, mx, o));
    float s = 0.f;
    #pragma unroll
    for (int i = 0; i < 16; i++) { v[i] = __expf(v[i] - mx); s += v[i]; }
    #pragma unroll
    for (int o = 16; o; o >>= 1) s += __shfl_xor_sync(0xffffffffu, s, o);
    float inv = 1.f / s;
    #pragma unroll
    for (int i = 0; i < 16; i++) sP[w][lane + 32 * i] = v[i] * inv;
    __syncthreads();
    #pragma unroll
    for (int i = 0; i < 4; i++) {
        int m = tid + 128 * i;
        float4 t = make_float4(sP[0][m], sP[1][m], sP[2][m], sP[3][m]);
        *(float4*)&g_probT[m * 512 + n0] = t;
    }
}

// message[d][n] = sum_m src[d][m] * probT[m][n]      grid (8,16), 256 thr
__global__ void __launch_bounds__(256) k_msg(const float* __restrict__ src)
{
    gemm_core<16, false>(src, g_probT, nullptr, nullptr, g_msg, 512, false);
}

// h2 = relu(wa @ [x; msg] + ba)                      grid (8,16), 256 thr
__global__ void __launch_bounds__(256) k_h2(
    const float* __restrict__ wa, const float* __restrict__ x,
    const float* __restrict__ ba)
{
    gemm_core<32, true>(wa, x, g_msg, ba, g_h2, 512, true);
}

// y = wb @ h2 + bb                                   grid (8,16), 256 thr
__global__ void __launch_bounds__(256) k_y(
    const float* __restrict__ wb, const float* __restrict__ bb,
    float* __restrict__ y)
{
    gemm_core<16, false>(wb, g_h2, nullptr, bb, y, 512, false);
}

// ---------------- launch ----------------
extern "C" void kernel_launch(void* const* d_in, const int* in_sizes, int n_in,
                              void* d_out, int out_size)
{
    const float* x   = (const float*)d_in[0];
    const float* src = (const float*)d_in[1];
    const float* w1  = (const float*)d_in[2];
    const float* b1  = (const float*)d_in[3];
    const float* w2  = (const float*)d_in[4];
    const float* b2  = (const float*)d_in[5];
    const float* wa  = (const float*)d_in[6];
    const float* ba  = (const float*)d_in[7];
    const float* wb  = (const float*)d_in[8];
    const float* bb  = (const float*)d_in[9];

    float* y      = (float*)d_out;   // (1, D, NQ)
    float* scores = y + D * NQ;      // (1, NQ, NK)

    k_qk      <<<dim3(8, 8, 2), 256>>>(w1, x, src, b1);
    k_score   <<<dim3(8, 16),   256>>>(w2, b2, scores);
    k_softmaxT<<<128,           128>>>(scores);
    k_msg     <<<dim3(8, 16),   256>>>(src);
    k_h2      <<<dim3(8, 16),   256>>>(wa, x, ba);
    k_y       <<<dim3(8, 16),   256>>>(wb, bb, y);
}